// round 2
// baseline (speedup 1.0000x reference)
#include <cuda_runtime.h>
#include <math.h>

#define B_ 2
#define S_ 8192
#define D_ 768
#define H_ 12
#define HD_ 64
#define W_ 256
#define DFF_ 3072
#define NROWS (B_*S_)   // 16384

// ---------------- scratch (device globals; no allocation allowed) -------------
__device__ float g_h [NROWS*D_];
__device__ float g_q [NROWS*D_];
__device__ float g_k [NROWS*D_];
__device__ float g_v [NROWS*D_];
__device__ float g_a [NROWS*D_];
__device__ float g_t [NROWS*D_];
__device__ float g_h2[NROWS*D_];
__device__ float g_s2[NROWS*D_];
__device__ float g_l3[NROWS*D_];
__device__ float g_ff[(size_t)NROWS*DFF_];

// ---------------- block reduction (sum, sumsq) over 256 threads ---------------
__device__ __forceinline__ float2 block_reduce2(float a, float b) {
    __shared__ float sa[8], sb[8];
    __syncthreads();   // protect smem reuse across successive calls
    #pragma unroll
    for (int o = 16; o > 0; o >>= 1) {
        a += __shfl_down_sync(0xffffffffu, a, o);
        b += __shfl_down_sync(0xffffffffu, b, o);
    }
    int w = threadIdx.x >> 5, l = threadIdx.x & 31;
    if (l == 0) { sa[w] = a; sb[w] = b; }
    __syncthreads();
    if (threadIdx.x < 32) {
        a = (l < 8) ? sa[l] : 0.f;
        b = (l < 8) ? sb[l] : 0.f;
        #pragma unroll
        for (int o = 4; o > 0; o >>= 1) {
            a += __shfl_down_sync(0xffffffffu, a, o);
            b += __shfl_down_sync(0xffffffffu, b, o);
        }
        if (l == 0) { sa[0] = a; sb[0] = b; }
    }
    __syncthreads();
    return make_float2(sa[0], sb[0]);
}

// ---------------- K1: hidden = ln(src,n1,1e-5); h = ln(hidden+pos+tt, emb, 1e-12)
__global__ void __launch_bounds__(256) k_emb_ln(
    const float* __restrict__ src,
    const float* __restrict__ n1s, const float* __restrict__ n1b,
    const float* __restrict__ pos, const float* __restrict__ tt,
    const float* __restrict__ es,  const float* __restrict__ eb,
    float* __restrict__ out)
{
    int row = blockIdx.x;
    int sidx = row & (S_ - 1);
    int tid = threadIdx.x;
    const float* x = src + (size_t)row * D_;
    float v[3];
    #pragma unroll
    for (int k = 0; k < 3; k++) v[k] = x[tid + 256*k];
    float s = v[0]+v[1]+v[2];
    float q = v[0]*v[0]+v[1]*v[1]+v[2]*v[2];
    float2 r = block_reduce2(s, q);
    float mean = r.x * (1.f/D_);
    float rstd = rsqrtf(r.y*(1.f/D_) - mean*mean + 1e-5f);
    float u[3];
    #pragma unroll
    for (int k = 0; k < 3; k++) {
        int c = tid + 256*k;
        u[k] = (v[k]-mean)*rstd*n1s[c] + n1b[c] + pos[(size_t)sidx*D_ + c] + tt[c];
    }
    s = u[0]+u[1]+u[2];
    q = u[0]*u[0]+u[1]*u[1]+u[2]*u[2];
    r = block_reduce2(s, q);
    mean = r.x * (1.f/D_);
    rstd = rsqrtf(r.y*(1.f/D_) - mean*mean + 1e-12f);
    float* o = out + (size_t)row * D_;
    #pragma unroll
    for (int k = 0; k < 3; k++) {
        int c = tid + 256*k;
        o[c] = (u[k]-mean)*rstd*es[c] + eb[c];
    }
}

// ---------------- plain LN ---------------------------------------------------
__global__ void __launch_bounds__(256) k_ln(
    const float* __restrict__ in, const float* __restrict__ sg,
    const float* __restrict__ bg, float eps, float* __restrict__ out)
{
    int row = blockIdx.x, tid = threadIdx.x;
    const float* x = in + (size_t)row * D_;
    float v[3];
    #pragma unroll
    for (int k = 0; k < 3; k++) v[k] = x[tid + 256*k];
    float s = v[0]+v[1]+v[2];
    float q = v[0]*v[0]+v[1]*v[1]+v[2]*v[2];
    float2 r = block_reduce2(s, q);
    float mean = r.x * (1.f/D_);
    float rstd = rsqrtf(r.y*(1.f/D_) - mean*mean + eps);
    float* o = out + (size_t)row * D_;
    #pragma unroll
    for (int k = 0; k < 3; k++) {
        int c = tid + 256*k;
        o[c] = (v[k]-mean)*rstd*sg[c] + bg[c];
    }
}

// ---- K8: a=ln(t,out_ln,1e-12); src2=src+a (store); l3=ln(src2,n2,1e-5) (store)
__global__ void __launch_bounds__(256) k_out_ln(
    const float* __restrict__ t,
    const float* __restrict__ os, const float* __restrict__ ob,
    const float* __restrict__ src,
    const float* __restrict__ n2s, const float* __restrict__ n2b,
    float* __restrict__ s2out, float* __restrict__ l3out)
{
    int row = blockIdx.x, tid = threadIdx.x;
    const float* x = t + (size_t)row * D_;
    float v[3];
    #pragma unroll
    for (int k = 0; k < 3; k++) v[k] = x[tid + 256*k];
    float s = v[0]+v[1]+v[2];
    float q = v[0]*v[0]+v[1]*v[1]+v[2]*v[2];
    float2 r = block_reduce2(s, q);
    float mean = r.x * (1.f/D_);
    float rstd = rsqrtf(r.y*(1.f/D_) - mean*mean + 1e-12f);
    const float* sr = src + (size_t)row * D_;
    float u[3];
    #pragma unroll
    for (int k = 0; k < 3; k++) {
        int c = tid + 256*k;
        float a = (v[k]-mean)*rstd*os[c] + ob[c];
        u[k] = sr[c] + a;
        s2out[(size_t)row*D_ + c] = u[k];
    }
    s = u[0]+u[1]+u[2];
    q = u[0]*u[0]+u[1]*u[1]+u[2]*u[2];
    r = block_reduce2(s, q);
    mean = r.x * (1.f/D_);
    rstd = rsqrtf(r.y*(1.f/D_) - mean*mean + 1e-5f);
    #pragma unroll
    for (int k = 0; k < 3; k++) {
        int c = tid + 256*k;
        l3out[(size_t)row*D_ + c] = (u[k]-mean)*rstd*n2s[c] + n2b[c];
    }
}

// ---------------- GEMM: C = A[M,K] @ W[K,N] + bias, epilogues -----------------
enum { EPI_STORE = 0, EPI_GELU = 1, EPI_RELU = 2, EPI_RESID = 3, EPI_QKV = 4 };

template<int EPI>
__global__ void __launch_bounds__(256) k_gemm(
    const float* __restrict__ A, const float* __restrict__ Wt,
    const float* __restrict__ bias, const float* __restrict__ resid,
    float* __restrict__ C, int M, int N, int K, float scale)
{
    __shared__ float As[8][132];   // padded: transposed A tile
    __shared__ float Bs[8][128];
    int tid = threadIdx.x;
    int bx = blockIdx.x, by = blockIdx.y;
    int tx = tid & 15, ty = tid >> 4;
    int aRow = tid >> 1,  aCol = (tid & 1) * 4;
    int bRow = tid >> 5,  bCol = (tid & 31) * 4;
    const float* Ap = A + (size_t)(by*128 + aRow)*K + aCol;
    const float* Bp = Wt + (size_t)bRow*N + bx*128 + bCol;
    float acc[8][8] = {};

    for (int k0 = 0; k0 < K; k0 += 8) {
        float4 av = *(const float4*)(Ap + k0);
        As[aCol+0][aRow] = av.x;
        As[aCol+1][aRow] = av.y;
        As[aCol+2][aRow] = av.z;
        As[aCol+3][aRow] = av.w;
        *(float4*)&Bs[bRow][bCol] = *(const float4*)(Bp + (size_t)k0*N);
        __syncthreads();
        #pragma unroll
        for (int k = 0; k < 8; k++) {
            float4 a0 = *(const float4*)&As[k][ty*8];
            float4 a1 = *(const float4*)&As[k][ty*8 + 4];
            float4 b0 = *(const float4*)&Bs[k][tx*4];
            float4 b1 = *(const float4*)&Bs[k][64 + tx*4];
            float af[8] = {a0.x,a0.y,a0.z,a0.w,a1.x,a1.y,a1.z,a1.w};
            float bf[8] = {b0.x,b0.y,b0.z,b0.w,b1.x,b1.y,b1.z,b1.w};
            #pragma unroll
            for (int i = 0; i < 8; i++)
                #pragma unroll
                for (int j = 0; j < 8; j++)
                    acc[i][j] += af[i]*bf[j];
        }
        __syncthreads();
    }

    float4 bias0 = *(const float4*)(bias + bx*128 + tx*4);
    float4 bias1 = *(const float4*)(bias + bx*128 + 64 + tx*4);

    #pragma unroll
    for (int i = 0; i < 8; i++) {
        int r = by*128 + ty*8 + i;
        #pragma unroll
        for (int strip = 0; strip < 2; strip++) {
            int c0 = bx*128 + strip*64 + tx*4;
            float4 bb = strip ? bias1 : bias0;
            float4 v;
            v.x = acc[i][strip*4+0] + bb.x;
            v.y = acc[i][strip*4+1] + bb.y;
            v.z = acc[i][strip*4+2] + bb.z;
            v.w = acc[i][strip*4+3] + bb.w;
            if (EPI == EPI_GELU) {
                v.x = 0.5f*v.x*(1.f + erff(v.x*0.70710678f));
                v.y = 0.5f*v.y*(1.f + erff(v.y*0.70710678f));
                v.z = 0.5f*v.z*(1.f + erff(v.z*0.70710678f));
                v.w = 0.5f*v.w*(1.f + erff(v.w*0.70710678f));
            } else if (EPI == EPI_RELU) {
                v.x = fmaxf(v.x, 0.f); v.y = fmaxf(v.y, 0.f);
                v.z = fmaxf(v.z, 0.f); v.w = fmaxf(v.w, 0.f);
            } else if (EPI == EPI_RESID) {
                float4 rr = *(const float4*)(resid + (size_t)r*N + c0);
                v.x += rr.x; v.y += rr.y; v.z += rr.z; v.w += rr.w;
            }
            if (EPI == EPI_QKV) {
                int head = c0 >> 6;          // 64 = HD_
                int hd   = c0 & 63;
                int bi_  = r >> 13;          // 8192 = S_
                int si   = r & (S_ - 1);
                v.x *= scale; v.y *= scale; v.z *= scale; v.w *= scale;
                *(float4*)(C + ((size_t)((bi_*H_ + head)*S_ + si))*HD_ + hd) = v;
            } else {
                *(float4*)(C + (size_t)r*N + c0) = v;
            }
        }
    }
}

// ---------------- band attention: one block per (chunk, head, batch) ----------
// Q/K/V in [B,H,S,HD]; output written directly to [B,S,D].
__global__ void __launch_bounds__(256, 1) k_band_attn(
    const float* __restrict__ Q, const float* __restrict__ Kg,
    const float* __restrict__ Vg, float* __restrict__ O)
{
    extern __shared__ float sm[];
    float* Ks = sm;                 // 64*64
    float* Vs = sm + 4096;          // 64*64
    float* Sc = sm + 8192;          // 256*65 (padded rows)
    int c = blockIdx.x, h = blockIdx.y, b = blockIdx.z;
    int i = threadIdx.x;            // query index within chunk
    int qpos = c*W_ + i;
    size_t base = ((size_t)(b*H_ + h)) * S_ * HD_;

    float q[64];
    {
        const float4* qr = (const float4*)(Q + base + (size_t)qpos*HD_);
        #pragma unroll
        for (int d = 0; d < 16; d++) {
            float4 t = qr[d];
            q[4*d] = t.x; q[4*d+1] = t.y; q[4*d+2] = t.z; q[4*d+3] = t.w;
        }
    }
    float acc[64];
    #pragma unroll
    for (int d = 0; d < 64; d++) acc[d] = 0.f;
    float m_run = -1e30f, l_run = 0.f;
    int kbase = c*W_ - W_;
    float* myS = Sc + i*65;

    for (int t = 0; t < 12; t++) {   // 12 tiles of 64 keys = 3*W
        int j0 = t*64;
        __syncthreads();
        #pragma unroll
        for (int p = 0; p < 4; p++) {
            int idx = i + p*256;
            int j = idx >> 4;
            int dg = (idx & 15) << 2;
            int kp = kbase + j0 + j;
            float4 kv = make_float4(0.f,0.f,0.f,0.f);
            float4 vv = make_float4(0.f,0.f,0.f,0.f);
            if (kp >= 0 && kp < S_) {
                kv = *(const float4*)(Kg + base + (size_t)kp*HD_ + dg);
                vv = *(const float4*)(Vg + base + (size_t)kp*HD_ + dg);
            }
            *(float4*)&Ks[j*64 + dg] = kv;
            *(float4*)&Vs[j*64 + dg] = vv;
        }
        __syncthreads();

        // pass 1: scores + tile max (scores staged in padded SMEM row)
        float mt = -1e30f;
        #pragma unroll 4
        for (int jj = 0; jj < 64; jj++) {
            int jg = j0 + jj;
            int kp = kbase + jg;
            const float4* kr = (const float4*)&Ks[jj*64];
            float s = 0.f;
            #pragma unroll
            for (int dg = 0; dg < 16; dg++) {
                float4 kv = kr[dg];
                s += q[4*dg]*kv.x + q[4*dg+1]*kv.y + q[4*dg+2]*kv.z + q[4*dg+3]*kv.w;
            }
            bool ok = (jg >= i) && (jg <= i + 2*W_) && (kp >= 0) && (kp < S_);
            s = ok ? s : -1e30f;
            if (s > mt) mt = s;
            myS[jj] = s;
        }
        if (mt > -0.5e30f) {   // tile has at least one valid key for this query
            float m_new = fmaxf(m_run, mt);
            float corr = __expf(m_run - m_new);
            #pragma unroll
            for (int d = 0; d < 64; d++) acc[d] *= corr;
            float lsum = 0.f;
            #pragma unroll 2
            for (int jj = 0; jj < 64; jj++) {
                float p = __expf(myS[jj] - m_new);
                lsum += p;
                const float4* vr = (const float4*)&Vs[jj*64];
                #pragma unroll
                for (int dg = 0; dg < 16; dg++) {
                    float4 vv = vr[dg];
                    acc[4*dg]   += p*vv.x;
                    acc[4*dg+1] += p*vv.y;
                    acc[4*dg+2] += p*vv.z;
                    acc[4*dg+3] += p*vv.w;
                }
            }
            l_run = l_run*corr + lsum;
            m_run = m_new;
        }
    }

    float inv = 1.f / l_run;
    float* orow = O + ((size_t)(b*S_ + qpos))*D_ + h*HD_;
    #pragma unroll
    for (int dg = 0; dg < 16; dg++) {
        float4 v;
        v.x = acc[4*dg]*inv;   v.y = acc[4*dg+1]*inv;
        v.z = acc[4*dg+2]*inv; v.w = acc[4*dg+3]*inv;
        *(float4*)(orow + 4*dg) = v;
    }
}

// ------------------------------- launcher -------------------------------------
extern "C" void kernel_launch(void* const* d_in, const int* in_sizes, int n_in,
                              void* d_out, int out_size)
{
    const float* src  = (const float*)d_in[0];
    const float* pos  = (const float*)d_in[1];
    const float* tt   = (const float*)d_in[2];
    const float* es   = (const float*)d_in[3];
    const float* eb   = (const float*)d_in[4];
    const float* wq   = (const float*)d_in[5];
    const float* bq   = (const float*)d_in[6];
    const float* wk   = (const float*)d_in[7];
    const float* bk   = (const float*)d_in[8];
    const float* wv   = (const float*)d_in[9];
    const float* bv   = (const float*)d_in[10];
    const float* wo   = (const float*)d_in[11];
    const float* bo   = (const float*)d_in[12];
    const float* atts = (const float*)d_in[13];
    const float* attb = (const float*)d_in[14];
    const float* wi   = (const float*)d_in[15];
    const float* bi   = (const float*)d_in[16];
    const float* wo2  = (const float*)d_in[17];
    const float* bo2  = (const float*)d_in[18];
    const float* outs = (const float*)d_in[19];
    const float* outb = (const float*)d_in[20];
    const float* n1s  = (const float*)d_in[21];
    const float* n1b  = (const float*)d_in[22];
    const float* n2s  = (const float*)d_in[23];
    const float* n2b  = (const float*)d_in[24];
    const float* w1   = (const float*)d_in[25];
    const float* b1   = (const float*)d_in[26];
    const float* w2   = (const float*)d_in[27];
    const float* b2   = (const float*)d_in[28];

    float *h, *q, *k, *v, *a, *t, *h2, *s2, *l3, *ff;
    cudaGetSymbolAddress((void**)&h,  g_h);
    cudaGetSymbolAddress((void**)&q,  g_q);
    cudaGetSymbolAddress((void**)&k,  g_k);
    cudaGetSymbolAddress((void**)&v,  g_v);
    cudaGetSymbolAddress((void**)&a,  g_a);
    cudaGetSymbolAddress((void**)&t,  g_t);
    cudaGetSymbolAddress((void**)&h2, g_h2);
    cudaGetSymbolAddress((void**)&s2, g_s2);
    cudaGetSymbolAddress((void**)&l3, g_l3);
    cudaGetSymbolAddress((void**)&ff, g_ff);

    const int ATTN_SMEM = (4096 + 4096 + 256*65) * 4;   // 99328 B
    cudaFuncSetAttribute(k_band_attn, cudaFuncAttributeMaxDynamicSharedMemorySize, ATTN_SMEM);

    dim3 blk(256);
    dim3 gD(D_/128, NROWS/128);      // (6, 128)
    dim3 gF(DFF_/128, NROWS/128);    // (24, 128)

    // 1. double-LN + embeddings
    k_emb_ln<<<NROWS, 256>>>(src, n1s, n1b, pos, tt, es, eb, h);
    // 2. QKV projections into [B,H,S,HD]
    k_gemm<EPI_QKV><<<gD, blk>>>(h, wq, bq, nullptr, q, NROWS, D_, D_, 0.125f);
    k_gemm<EPI_QKV><<<gD, blk>>>(h, wk, bk, nullptr, k, NROWS, D_, D_, 1.f);
    k_gemm<EPI_QKV><<<gD, blk>>>(h, wv, bv, nullptr, v, NROWS, D_, D_, 1.f);
    // 3. band attention -> [B,S,D]
    k_band_attn<<<dim3(S_/W_, H_, B_), 256, ATTN_SMEM>>>(q, k, v, a);
    // 4. attn out proj + residual(h)
    k_gemm<EPI_RESID><<<gD, blk>>>(a, wo, bo, h, t, NROWS, D_, D_, 1.f);
    // 5. attn LN
    k_ln<<<NROWS, 256>>>(t, atts, attb, 1e-12f, h2);
    // 6. FFN1 + gelu
    k_gemm<EPI_GELU><<<gF, blk>>>(h2, wi, bi, nullptr, ff, NROWS, DFF_, D_, 1.f);
    // 7. FFN2 + residual(h2)
    k_gemm<EPI_RESID><<<gD, blk>>>(ff, wo2, bo2, h2, t, NROWS, D_, DFF_, 1.f);
    // 8. out LN, src2 = src + ln(...), l3 = ln(src2, n2, 1e-5)
    k_out_ln<<<NROWS, 256>>>(t, outs, outb, src, n2s, n2b, s2, l3);
    // 9. second-FFN 1 + relu
    k_gemm<EPI_RELU><<<gF, blk>>>(l3, w1, b1, nullptr, ff, NROWS, DFF_, D_, 1.f);
    // 10. second-FFN 2 + residual(src2) -> output
    k_gemm<EPI_RESID><<<gD, blk>>>(ff, w2, b2, s2, (float*)d_out, NROWS, D_, DFF_, 1.f);
}

// round 4
// speedup vs baseline: 1.9770x; 1.9770x over previous
#include <cuda_runtime.h>
#include <stdint.h>
#include <math.h>

#define B_ 2
#define S_ 8192
#define D_ 768
#define H_ 12
#define HD_ 64
#define W_ 256
#define DFF_ 3072
#define NROWS (B_*S_)   // 16384

// ---------------- scratch (device globals; no allocation allowed) -------------
__device__ float g_h [NROWS*D_];
__device__ float g_q [NROWS*D_];
__device__ float g_k [NROWS*D_];
__device__ float g_v [NROWS*D_];
__device__ float g_a [NROWS*D_];
__device__ float g_t [NROWS*D_];
__device__ float g_h2[NROWS*D_];
__device__ float g_s2[NROWS*D_];
__device__ float g_l3[NROWS*D_];
__device__ float g_ff[(size_t)NROWS*DFF_];

// ---------------- helpers ------------------------------------------------------
__device__ __forceinline__ uint32_t smem_u32(const void* p) {
    return (uint32_t)__cvta_generic_to_shared(p);
}
__device__ __forceinline__ void cp16(uint32_t dst, const void* src) {
    asm volatile("cp.async.cg.shared.global [%0], [%1], 16;\n" :: "r"(dst), "l"(src));
}
__device__ __forceinline__ void cp_commit() {
    asm volatile("cp.async.commit_group;\n");
}
__device__ __forceinline__ void cp_wait0() {
    asm volatile("cp.async.wait_group 0;\n");
}
__device__ __forceinline__ uint32_t f2tf(float f) {
    uint32_t u;
    asm("cvt.rna.tf32.f32 %0, %1;\n" : "=r"(u) : "f"(f));
    return u;
}
__device__ __forceinline__ void mma_tf32(float* c, const uint32_t* a, const uint32_t* b) {
    asm volatile(
        "mma.sync.aligned.m16n8k8.row.col.f32.tf32.tf32.f32 "
        "{%0,%1,%2,%3}, {%4,%5,%6,%7}, {%8,%9}, {%0,%1,%2,%3};\n"
        : "+f"(c[0]), "+f"(c[1]), "+f"(c[2]), "+f"(c[3])
        : "r"(a[0]), "r"(a[1]), "r"(a[2]), "r"(a[3]), "r"(b[0]), "r"(b[1]));
}

// ---------------- block reduction (sum, sumsq) over 256 threads ---------------
__device__ __forceinline__ float2 block_reduce2(float a, float b) {
    __shared__ float sa[8], sb[8];
    __syncthreads();
    #pragma unroll
    for (int o = 16; o > 0; o >>= 1) {
        a += __shfl_down_sync(0xffffffffu, a, o);
        b += __shfl_down_sync(0xffffffffu, b, o);
    }
    int w = threadIdx.x >> 5, l = threadIdx.x & 31;
    if (l == 0) { sa[w] = a; sb[w] = b; }
    __syncthreads();
    if (threadIdx.x < 32) {
        a = (l < 8) ? sa[l] : 0.f;
        b = (l < 8) ? sb[l] : 0.f;
        #pragma unroll
        for (int o = 4; o > 0; o >>= 1) {
            a += __shfl_down_sync(0xffffffffu, a, o);
            b += __shfl_down_sync(0xffffffffu, b, o);
        }
        if (l == 0) { sa[0] = a; sb[0] = b; }
    }
    __syncthreads();
    return make_float2(sa[0], sb[0]);
}

// ---------------- K1: hidden = ln(src,n1,1e-5); h = ln(hidden+pos+tt, emb, 1e-12)
__global__ void __launch_bounds__(256) k_emb_ln(
    const float* __restrict__ src,
    const float* __restrict__ n1s, const float* __restrict__ n1b,
    const float* __restrict__ pos, const float* __restrict__ tt,
    const float* __restrict__ es,  const float* __restrict__ eb,
    float* __restrict__ out)
{
    int row = blockIdx.x;
    int sidx = row & (S_ - 1);
    int tid = threadIdx.x;
    const float* x = src + (size_t)row * D_;
    float v[3];
    #pragma unroll
    for (int k = 0; k < 3; k++) v[k] = x[tid + 256*k];
    float s = v[0]+v[1]+v[2];
    float q = v[0]*v[0]+v[1]*v[1]+v[2]*v[2];
    float2 r = block_reduce2(s, q);
    float mean = r.x * (1.f/D_);
    float rstd = rsqrtf(r.y*(1.f/D_) - mean*mean + 1e-5f);
    float u[3];
    #pragma unroll
    for (int k = 0; k < 3; k++) {
        int c = tid + 256*k;
        u[k] = (v[k]-mean)*rstd*n1s[c] + n1b[c] + pos[(size_t)sidx*D_ + c] + tt[c];
    }
    s = u[0]+u[1]+u[2];
    q = u[0]*u[0]+u[1]*u[1]+u[2]*u[2];
    r = block_reduce2(s, q);
    mean = r.x * (1.f/D_);
    rstd = rsqrtf(r.y*(1.f/D_) - mean*mean + 1e-12f);
    float* o = out + (size_t)row * D_;
    #pragma unroll
    for (int k = 0; k < 3; k++) {
        int c = tid + 256*k;
        o[c] = (u[k]-mean)*rstd*es[c] + eb[c];
    }
}

// ---------------- plain LN ---------------------------------------------------
__global__ void __launch_bounds__(256) k_ln(
    const float* __restrict__ in, const float* __restrict__ sg,
    const float* __restrict__ bg, float eps, float* __restrict__ out)
{
    int row = blockIdx.x, tid = threadIdx.x;
    const float* x = in + (size_t)row * D_;
    float v[3];
    #pragma unroll
    for (int k = 0; k < 3; k++) v[k] = x[tid + 256*k];
    float s = v[0]+v[1]+v[2];
    float q = v[0]*v[0]+v[1]*v[1]+v[2]*v[2];
    float2 r = block_reduce2(s, q);
    float mean = r.x * (1.f/D_);
    float rstd = rsqrtf(r.y*(1.f/D_) - mean*mean + eps);
    float* o = out + (size_t)row * D_;
    #pragma unroll
    for (int k = 0; k < 3; k++) {
        int c = tid + 256*k;
        o[c] = (v[k]-mean)*rstd*sg[c] + bg[c];
    }
}

// ---- K8: a=ln(t,out_ln,1e-12); src2=src+a (store); l3=ln(src2,n2,1e-5) (store)
__global__ void __launch_bounds__(256) k_out_ln(
    const float* __restrict__ t,
    const float* __restrict__ os, const float* __restrict__ ob,
    const float* __restrict__ src,
    const float* __restrict__ n2s, const float* __restrict__ n2b,
    float* __restrict__ s2out, float* __restrict__ l3out)
{
    int row = blockIdx.x, tid = threadIdx.x;
    const float* x = t + (size_t)row * D_;
    float v[3];
    #pragma unroll
    for (int k = 0; k < 3; k++) v[k] = x[tid + 256*k];
    float s = v[0]+v[1]+v[2];
    float q = v[0]*v[0]+v[1]*v[1]+v[2]*v[2];
    float2 r = block_reduce2(s, q);
    float mean = r.x * (1.f/D_);
    float rstd = rsqrtf(r.y*(1.f/D_) - mean*mean + 1e-12f);
    const float* sr = src + (size_t)row * D_;
    float u[3];
    #pragma unroll
    for (int k = 0; k < 3; k++) {
        int c = tid + 256*k;
        float a = (v[k]-mean)*rstd*os[c] + ob[c];
        u[k] = sr[c] + a;
        s2out[(size_t)row*D_ + c] = u[k];
    }
    s = u[0]+u[1]+u[2];
    q = u[0]*u[0]+u[1]*u[1]+u[2]*u[2];
    r = block_reduce2(s, q);
    mean = r.x * (1.f/D_);
    rstd = rsqrtf(r.y*(1.f/D_) - mean*mean + 1e-5f);
    #pragma unroll
    for (int k = 0; k < 3; k++) {
        int c = tid + 256*k;
        l3out[(size_t)row*D_ + c] = (u[k]-mean)*rstd*n2s[c] + n2b[c];
    }
}

// ---------------- tensor-core GEMM: C = A[M,K] @ W[K,N] + bias, epilogues -----
// tf32 mma.sync m16n8k8, fp32 accumulate. 128x128x16 CTA tile, 8 warps of 64x32.
enum { EPI_STORE = 0, EPI_GELU = 1, EPI_RELU = 2, EPI_RESID = 3, EPI_QKV = 4 };

#define SA 20    // As row stride (floats): banks (g*20+tig)%32 all-distinct
#define SB 136   // Bs row stride (floats): banks (tig*8+g)%32 all-distinct

template<int EPI>
__global__ void __launch_bounds__(256) k_gemm_tc(
    const float* __restrict__ A, const float* __restrict__ Wt,
    const float* __restrict__ bias, const float* __restrict__ resid,
    float* __restrict__ C, int M, int N, int K, float scale)
{
    __shared__ float As[2][128*SA];
    __shared__ float Bs[2][16*SB];

    int tid = threadIdx.x;
    int bx = blockIdx.x, by = blockIdx.y;
    int wid = tid >> 5, lane = tid & 31;
    int g = lane >> 2, tig = lane & 3;
    int wm = (wid & 1) * 64;       // warp m offset within CTA tile
    int wn = (wid >> 1) * 32;      // warp n offset within CTA tile

    // global load assignments
    int ar = tid >> 1, ac = (tid & 1) * 8;    // A: 128 rows x 16 floats
    int br = tid >> 4, bc = (tid & 15) * 8;   // B: 16 rows x 128 floats
    const float* Ag = A  + (size_t)(by*128 + ar)*K + ac;
    const float* Bg = Wt + (size_t)br*N + bx*128 + bc;
    uint32_t AsD[2], BsD[2];
    #pragma unroll
    for (int s = 0; s < 2; s++) {
        AsD[s] = smem_u32(&As[s][ar*SA + ac]);
        BsD[s] = smem_u32(&Bs[s][br*SB + bc]);
    }

    float acc[4][4][4];
    #pragma unroll
    for (int mi = 0; mi < 4; mi++)
        #pragma unroll
        for (int ni = 0; ni < 4; ni++)
            #pragma unroll
            for (int e = 0; e < 4; e++) acc[mi][ni][e] = 0.f;

    // prefetch stage 0
    cp16(AsD[0],      Ag);
    cp16(AsD[0] + 16, Ag + 4);
    cp16(BsD[0],      Bg);
    cp16(BsD[0] + 16, Bg + 4);
    cp_commit();

    int NIT = K >> 4;
    for (int it = 0; it < NIT; it++) {
        int cb = it & 1;
        cp_wait0();
        __syncthreads();
        if (it + 1 < NIT) {
            int nb = cb ^ 1;
            int k0 = (it + 1) << 4;
            cp16(AsD[nb],      Ag + k0);
            cp16(AsD[nb] + 16, Ag + k0 + 4);
            cp16(BsD[nb],      Bg + (size_t)k0*N);
            cp16(BsD[nb] + 16, Bg + (size_t)k0*N + 4);
            cp_commit();
        }
        #pragma unroll
        for (int kk = 0; kk < 2; kk++) {
            int k0 = kk * 8;
            uint32_t af[4][4], bf[4][2];
            #pragma unroll
            for (int mi = 0; mi < 4; mi++) {
                const float* ap = &As[cb][(wm + mi*16 + g)*SA + k0 + tig];
                af[mi][0] = f2tf(ap[0]);
                af[mi][1] = f2tf(ap[8*SA]);
                af[mi][2] = f2tf(ap[4]);
                af[mi][3] = f2tf(ap[8*SA + 4]);
            }
            #pragma unroll
            for (int ni = 0; ni < 4; ni++) {
                const float* bp = &Bs[cb][(k0 + tig)*SB + wn + ni*8 + g];
                bf[ni][0] = f2tf(bp[0]);
                bf[ni][1] = f2tf(bp[4*SB]);
            }
            #pragma unroll
            for (int mi = 0; mi < 4; mi++)
                #pragma unroll
                for (int ni = 0; ni < 4; ni++)
                    mma_tf32(acc[mi][ni], af[mi], bf[ni]);
        }
        __syncthreads();
    }

    // ----- epilogue -----
    #pragma unroll
    for (int mi = 0; mi < 4; mi++) {
        int r0 = by*128 + wm + mi*16 + g;
        #pragma unroll
        for (int ni = 0; ni < 4; ni++) {
            int c = bx*128 + wn + ni*8 + tig*2;
            float2 bb = *(const float2*)(bias + c);
            #pragma unroll
            for (int half = 0; half < 2; half++) {
                int r = r0 + half*8;
                float2 v;
                v.x = acc[mi][ni][half*2 + 0] + bb.x;
                v.y = acc[mi][ni][half*2 + 1] + bb.y;
                if (EPI == EPI_GELU) {
                    v.x = 0.5f*v.x*(1.f + erff(v.x*0.70710678f));
                    v.y = 0.5f*v.y*(1.f + erff(v.y*0.70710678f));
                } else if (EPI == EPI_RELU) {
                    v.x = fmaxf(v.x, 0.f);
                    v.y = fmaxf(v.y, 0.f);
                } else if (EPI == EPI_RESID) {
                    float2 rr = *(const float2*)(resid + (size_t)r*N + c);
                    v.x += rr.x; v.y += rr.y;
                }
                if (EPI == EPI_QKV) {
                    int head = c >> 6;
                    int hd   = c & 63;
                    int bi_  = r >> 13;
                    int si   = r & (S_ - 1);
                    v.x *= scale; v.y *= scale;
                    *(float2*)(C + ((size_t)((bi_*H_ + head)*S_ + si))*HD_ + hd) = v;
                } else {
                    *(float2*)(C + (size_t)r*N + c) = v;
                }
            }
        }
    }
}

// ---------------- band attention: one block per (chunk, head, batch) ----------
__global__ void __launch_bounds__(256, 1) k_band_attn(
    const float* __restrict__ Q, const float* __restrict__ Kg,
    const float* __restrict__ Vg, float* __restrict__ O)
{
    extern __shared__ float sm[];
    float* Ks = sm;                 // 64*64
    float* Vs = sm + 4096;          // 64*64
    float* Sc = sm + 8192;          // 256*65 (padded rows)
    int c = blockIdx.x, h = blockIdx.y, b = blockIdx.z;
    int i = threadIdx.x;            // query index within chunk
    int qpos = c*W_ + i;
    size_t base = ((size_t)(b*H_ + h)) * S_ * HD_;

    float q[64];
    {
        const float4* qr = (const float4*)(Q + base + (size_t)qpos*HD_);
        #pragma unroll
        for (int d = 0; d < 16; d++) {
            float4 t = qr[d];
            q[4*d] = t.x; q[4*d+1] = t.y; q[4*d+2] = t.z; q[4*d+3] = t.w;
        }
    }
    float acc[64];
    #pragma unroll
    for (int d = 0; d < 64; d++) acc[d] = 0.f;
    float m_run = -1e30f, l_run = 0.f;
    int kbase = c*W_ - W_;
    float* myS = Sc + i*65;

    for (int t = 0; t < 12; t++) {
        int j0 = t*64;
        __syncthreads();
        #pragma unroll
        for (int p = 0; p < 4; p++) {
            int idx = i + p*256;
            int j = idx >> 4;
            int dg = (idx & 15) << 2;
            int kp = kbase + j0 + j;
            float4 kv = make_float4(0.f,0.f,0.f,0.f);
            float4 vv = make_float4(0.f,0.f,0.f,0.f);
            if (kp >= 0 && kp < S_) {
                kv = *(const float4*)(Kg + base + (size_t)kp*HD_ + dg);
                vv = *(const float4*)(Vg + base + (size_t)kp*HD_ + dg);
            }
            *(float4*)&Ks[j*64 + dg] = kv;
            *(float4*)&Vs[j*64 + dg] = vv;
        }
        __syncthreads();

        float mt = -1e30f;
        #pragma unroll 4
        for (int jj = 0; jj < 64; jj++) {
            int jg = j0 + jj;
            int kp = kbase + jg;
            const float4* kr = (const float4*)&Ks[jj*64];
            float s = 0.f;
            #pragma unroll
            for (int dg = 0; dg < 16; dg++) {
                float4 kv = kr[dg];
                s += q[4*dg]*kv.x + q[4*dg+1]*kv.y + q[4*dg+2]*kv.z + q[4*dg+3]*kv.w;
            }
            bool ok = (jg >= i) && (jg <= i + 2*W_) && (kp >= 0) && (kp < S_);
            s = ok ? s : -1e30f;
            if (s > mt) mt = s;
            myS[jj] = s;
        }
        if (mt > -0.5e30f) {
            float m_new = fmaxf(m_run, mt);
            float corr = __expf(m_run - m_new);
            #pragma unroll
            for (int d = 0; d < 64; d++) acc[d] *= corr;
            float lsum = 0.f;
            #pragma unroll 2
            for (int jj = 0; jj < 64; jj++) {
                float p = __expf(myS[jj] - m_new);
                lsum += p;
                const float4* vr = (const float4*)&Vs[jj*64];
                #pragma unroll
                for (int dg = 0; dg < 16; dg++) {
                    float4 vv = vr[dg];
                    acc[4*dg]   += p*vv.x;
                    acc[4*dg+1] += p*vv.y;
                    acc[4*dg+2] += p*vv.z;
                    acc[4*dg+3] += p*vv.w;
                }
            }
            l_run = l_run*corr + lsum;
            m_run = m_new;
        }
    }

    float inv = 1.f / l_run;
    float* orow = O + ((size_t)(b*S_ + qpos))*D_ + h*HD_;
    #pragma unroll
    for (int dg = 0; dg < 16; dg++) {
        float4 v;
        v.x = acc[4*dg]*inv;   v.y = acc[4*dg+1]*inv;
        v.z = acc[4*dg+2]*inv; v.w = acc[4*dg+3]*inv;
        *(float4*)(orow + 4*dg) = v;
    }
}

// ------------------------------- launcher -------------------------------------
extern "C" void kernel_launch(void* const* d_in, const int* in_sizes, int n_in,
                              void* d_out, int out_size)
{
    const float* src  = (const float*)d_in[0];
    const float* pos  = (const float*)d_in[1];
    const float* tt   = (const float*)d_in[2];
    const float* es   = (const float*)d_in[3];
    const float* eb   = (const float*)d_in[4];
    const float* wq   = (const float*)d_in[5];
    const float* bq   = (const float*)d_in[6];
    const float* wk   = (const float*)d_in[7];
    const float* bk   = (const float*)d_in[8];
    const float* wv   = (const float*)d_in[9];
    const float* bv   = (const float*)d_in[10];
    const float* wo   = (const float*)d_in[11];
    const float* bo   = (const float*)d_in[12];
    const float* atts = (const float*)d_in[13];
    const float* attb = (const float*)d_in[14];
    const float* wi   = (const float*)d_in[15];
    const float* bi   = (const float*)d_in[16];
    const float* wo2  = (const float*)d_in[17];
    const float* bo2  = (const float*)d_in[18];
    const float* outs = (const float*)d_in[19];
    const float* outb = (const float*)d_in[20];
    const float* n1s  = (const float*)d_in[21];
    const float* n1b  = (const float*)d_in[22];
    const float* n2s  = (const float*)d_in[23];
    const float* n2b  = (const float*)d_in[24];
    const float* w1   = (const float*)d_in[25];
    const float* b1   = (const float*)d_in[26];
    const float* w2   = (const float*)d_in[27];
    const float* b2   = (const float*)d_in[28];

    float *h, *q, *k, *v, *a, *t, *h2, *s2, *l3, *ff;
    cudaGetSymbolAddress((void**)&h,  g_h);
    cudaGetSymbolAddress((void**)&q,  g_q);
    cudaGetSymbolAddress((void**)&k,  g_k);
    cudaGetSymbolAddress((void**)&v,  g_v);
    cudaGetSymbolAddress((void**)&a,  g_a);
    cudaGetSymbolAddress((void**)&t,  g_t);
    cudaGetSymbolAddress((void**)&h2, g_h2);
    cudaGetSymbolAddress((void**)&s2, g_s2);
    cudaGetSymbolAddress((void**)&l3, g_l3);
    cudaGetSymbolAddress((void**)&ff, g_ff);

    const int ATTN_SMEM = (4096 + 4096 + 256*65) * 4;   // 99328 B
    cudaFuncSetAttribute(k_band_attn, cudaFuncAttributeMaxDynamicSharedMemorySize, ATTN_SMEM);

    dim3 blk(256);
    dim3 gD(D_/128, NROWS/128);      // (6, 128)
    dim3 gF(DFF_/128, NROWS/128);    // (24, 128)

    // 1. double-LN + embeddings
    k_emb_ln<<<NROWS, 256>>>(src, n1s, n1b, pos, tt, es, eb, h);
    // 2. QKV projections into [B,H,S,HD]
    k_gemm_tc<EPI_QKV><<<gD, blk>>>(h, wq, bq, nullptr, q, NROWS, D_, D_, 0.125f);
    k_gemm_tc<EPI_QKV><<<gD, blk>>>(h, wk, bk, nullptr, k, NROWS, D_, D_, 1.f);
    k_gemm_tc<EPI_QKV><<<gD, blk>>>(h, wv, bv, nullptr, v, NROWS, D_, D_, 1.f);
    // 3. band attention -> [B,S,D]
    k_band_attn<<<dim3(S_/W_, H_, B_), 256, ATTN_SMEM>>>(q, k, v, a);
    // 4. attn out proj + residual(h)
    k_gemm_tc<EPI_RESID><<<gD, blk>>>(a, wo, bo, h, t, NROWS, D_, D_, 1.f);
    // 5. attn LN
    k_ln<<<NROWS, 256>>>(t, atts, attb, 1e-12f, h2);
    // 6. FFN1 + gelu
    k_gemm_tc<EPI_GELU><<<gF, blk>>>(h2, wi, bi, nullptr, ff, NROWS, DFF_, D_, 1.f);
    // 7. FFN2 + residual(h2)
    k_gemm_tc<EPI_RESID><<<gD, blk>>>(ff, wo2, bo2, h2, t, NROWS, D_, DFF_, 1.f);
    // 8. out LN, src2 = src + ln(...), l3 = ln(src2, n2, 1e-5)
    k_out_ln<<<NROWS, 256>>>(t, outs, outb, src, n2s, n2b, s2, l3);
    // 9. second-FFN 1 + relu
    k_gemm_tc<EPI_RELU><<<gF, blk>>>(l3, w1, b1, nullptr, ff, NROWS, DFF_, D_, 1.f);
    // 10. second-FFN 2 + residual(src2) -> output
    k_gemm_tc<EPI_RESID><<<gD, blk>>>(ff, w2, b2, s2, (float*)d_out, NROWS, D_, DFF_, 1.f);
}